// round 16
// baseline (speedup 1.0000x reference)
#include <cuda_runtime.h>
#include <cuda_fp16.h>
#include <cstdint>

typedef unsigned long long u64;

namespace {
constexpr int B_ = 256, T_ = 128, SD_ = 8, AD_ = 2, H_ = 3, K_ = 4, HID_ = 256;
constexpr int QD_ = SD_ + AD_;    // 10
constexpr int HK_ = H_ * K_;      // 12
constexpr int FEAT_ = HK_ + QD_;  // 22
constexpr int MT_ = 128;          // tokens per batch
constexpr int KP_ = 64;           // main-GEMM K panel
constexpr int ASTRIDE = 264;      // fp16 elems per A row (256 + 8 pad) -> 528B
}

// fp16(W2), produced by wsplit_kernel, consumed after griddepcontrol.wait
__device__ __half g_W2h[HID_ * HID_];

// ---------------- helpers ----------------
__device__ __forceinline__ uint32_t smem_u32(const void* p) {
    uint32_t a;
    asm("{ .reg .u64 t; cvta.to.shared.u64 t, %1; cvt.u32.u64 %0, t; }" : "=r"(a) : "l"(p));
    return a;
}
__device__ __forceinline__ void ldsm4(uint32_t r[4], uint32_t addr) {
    asm volatile("ldmatrix.sync.aligned.m8n8.x4.shared.b16 {%0,%1,%2,%3}, [%4];"
                 : "=r"(r[0]), "=r"(r[1]), "=r"(r[2]), "=r"(r[3]) : "r"(addr));
}
__device__ __forceinline__ void mma16816(float c[4], const uint32_t a[4],
                                         uint32_t b0, uint32_t b1) {
    asm volatile(
        "mma.sync.aligned.m16n8k16.row.col.f32.f16.f16.f32 "
        "{%0,%1,%2,%3}, {%4,%5,%6,%7}, {%8,%9}, {%0,%1,%2,%3};"
        : "+f"(c[0]), "+f"(c[1]), "+f"(c[2]), "+f"(c[3])
        : "r"(a[0]), "r"(a[1]), "r"(a[2]), "r"(a[3]), "r"(b0), "r"(b1));
}
__device__ __forceinline__ void cp_async16(uint32_t dst, const void* src) {
    asm volatile("cp.async.ca.shared.global [%0], [%1], 16;" :: "r"(dst), "l"(src) : "memory");
}
__device__ __forceinline__ uint32_t packh2(float lo, float hi) {
    __half2 h = __floats2half2_rn(lo, hi);
    return *(uint32_t*)&h;
}

// ---------------------------------------------------------------------------
// Prep (overlapped via PDL): W2 -> fp16, float4-vectorized, grid 64.
// ---------------------------------------------------------------------------
__global__ __launch_bounds__(256) void wsplit_kernel(const float* __restrict__ W2) {
    const int gid = blockIdx.x * 256 + threadIdx.x;
    const float4 w4 = ((const float4*)W2)[gid];
    ((__half2*)g_W2h)[gid * 2]     = __floats2half2_rn(w4.x, w4.y);
    ((__half2*)g_W2h)[gid * 2 + 1] = __floats2half2_rn(w4.z, w4.w);
}

// ---------------------------------------------------------------------------
// Fused kernel: one CTA = TWO batches, grid 128 (one wave), 256 threads.
//   A: attention(b0); b1 projections (q1 in regs, K/V(b1) to smem).
//   B: W1(b0); GEMM(b0) with attention(b1) interleaved into MMA dead slots.
//   C: epilogue(b0); finalize(b1); W1(b1); GEMM(b1); epilogue(b1).
// ---------------------------------------------------------------------------
__global__ __launch_bounds__(256) void fused_kernel(
    const float* __restrict__ state, const float* __restrict__ action,
    const float* __restrict__ Wk, const float* __restrict__ Wq,
    const float* __restrict__ Wv,
    const float* __restrict__ W1, const float* __restrict__ b1v,
    const float* __restrict__ b2, const float* __restrict__ Wout,
    const float* __restrict__ bout, float* __restrict__ out)
{
    extern __shared__ char smem[];
    constexpr int OFF_A   = 0;                    // 67584 (A tile; aliased in phase A)
    constexpr int BPANEL  = HID_ * KP_ * 2;       // 32768
    constexpr int OFF_B   = 67584;                // 2 bufs -> 133120
    constexpr int OFF_W1T = 133120;               // 16384
    constexpr int OFF_F0  = 149504;               // 8192
    constexpr int OFF_F1  = 157696;               // 8192
    constexpr int OFF_SK1 = 165888;               // 6144
    constexpr int OFF_SV1 = 172032;               // 6144
    constexpr int OFF_PA1 = 178176;               // 7680
    constexpr int OFF_BW  = 185856;               // 2048
    constexpr int OFF_B1s = 187904;               // 1024
    constexpr int OFF_RED = 188928;               // 512
    // aliases inside A region (phase A only)
    constexpr int OFF_SK0 = 0, OFF_SV0 = 6144, OFF_PA0 = 12288;

    const uint32_t sb = smem_u32(smem);
    const int tid = threadIdx.x, wid = tid >> 5, ln = tid & 31;
    const int b0 = blockIdx.x * 2, b1 = b0 + 1;

    float2* sBW = (float2*)(smem + OFF_BW);
    float* sB1 = (float*)(smem + OFF_B1s);
    float* sred = (float*)(smem + OFF_RED);

    // ---- B panel staging from g_W2h ----
    const int srow0 = tid >> 3, sc = tid & 7;
    const int scx = (sc ^ (srow0 & 7)) << 4;
    auto stageB = [&](int p, int buf) {
        const uint32_t dbase = sb + OFF_B + (uint32_t)(buf * BPANEL + scx);
        const int goff = srow0 * HID_ + p * KP_ + sc * 8;
#pragma unroll
        for (int j = 0; j < 8; j++)
            cp_async16(dbase + (uint32_t)((srow0 + j * 32) * 128),
                       g_W2h + goff + j * 32 * HID_);
        asm volatile("cp.async.commit_group;" ::: "memory");
    };

    // ---- prologue: W1 convert, feat zeros, misc ----
    {
        const float2* w1row = (const float2*)(W1 + tid * FEAT_);
        uint32_t h[16];
#pragma unroll
        for (int i = 0; i < 11; i++) {
            const float2 w = w1row[i];
            h[i] = packh2(w.x, w.y);
        }
#pragma unroll
        for (int i = 11; i < 16; i++) h[i] = 0u;
#pragma unroll
        for (int c = 0; c < 4; c++) {
            uint4 v = make_uint4(h[4 * c], h[4 * c + 1], h[4 * c + 2], h[4 * c + 3]);
            *(uint4*)(smem + OFF_W1T + tid * 64 + ((c ^ ((tid >> 1) & 3)) << 4)) = v;
        }
    }
    {
        float4* z = (float4*)(smem + OFF_F0);  // zeros F0 and F1 (contiguous 16KB)
#pragma unroll
        for (int i = 0; i < 4; i++) z[tid + i * 256] = make_float4(0.f, 0.f, 0.f, 0.f);
    }
    sBW[tid] = make_float2(b2[tid], Wout[tid]);
    sB1[tid] = b1v[tid];
    if (tid < MT_) sred[tid] = 0.f;

    const int half = tid >> 7, t = tid & 127;

    // feat write helper (single fp16 into swizzled [128][32] tile)
    auto featw = [&](int offF, int tt, int c, float v) {
        const uint32_t ad = (uint32_t)(tt * 64 + (((c >> 3) ^ ((tt >> 1) & 3)) << 4) +
                                       (c & 7) * 2);
        *(__half*)(smem + offF + ad) = __float2half_rn(v);
    };

    // ================= phase A: attention(b0) =================
    {
        float (*sK)[HK_] = (float(*)[HK_])(smem + OFF_SK0);
        float (*sV)[HK_] = (float(*)[HK_])(smem + OFF_SV0);
        float (*sPA)[MT_] = (float(*)[MT_])(smem + OFF_PA0);
        float qs[QD_], q[HK_], kp[HK_], vp[HK_];
        {
            const float* st = state + (size_t)(b0 * T_ + t) * SD_;
            const float* ac = action + (size_t)(b0 * T_ + t) * AD_;
#pragma unroll
            for (int c = 0; c < SD_; c++) qs[c] = st[c];
            qs[SD_] = ac[0];
            qs[SD_ + 1] = ac[1];
#pragma unroll
            for (int i = 0; i < HK_; i++) {
                float a = 0.f;
#pragma unroll
                for (int c = 0; c < QD_; c++) a = fmaf(qs[c], Wq[i * QD_ + c], a);
                q[i] = 0.5f * a;   // fold 1/sqrt(K) into q
            }
#pragma unroll
            for (int i = 0; i < HK_; i++) {
                float ak = 0.f, av = 0.f;
#pragma unroll
                for (int c = 0; c < K_; c++) {
                    ak = fmaf(qs[c], Wk[i * K_ + c], ak);
                    av = fmaf(qs[c], Wv[i * K_ + c], av);
                }
                kp[i] = ak; vp[i] = av;
            }
            if (half == 0) {
#pragma unroll
                for (int i = 0; i < HK_; i++) { sK[t][i] = kp[i]; sV[t][i] = vp[i]; }
            }
        }
        __syncthreads();
        float sum0 = 0.f, sum1 = 0.f, sum2 = 0.f;
        float acc[HK_];
#pragma unroll
        for (int i = 0; i < HK_; i++) acc[i] = 0.f;
        const int j0 = half * 64;
#pragma unroll 4
        for (int jx = 0; jx < 64; jx++) {
            const int jj = j0 + jx;
            const float4 k0 = *(const float4*)&sK[jj][0];
            const float4 k1 = *(const float4*)&sK[jj][4];
            const float4 k2 = *(const float4*)&sK[jj][8];
            float s0 = q[0]*k0.x + q[1]*k0.y + q[2]*k0.z + q[3]*k0.w;
            float s1 = q[4]*k1.x + q[5]*k1.y + q[6]*k1.z + q[7]*k1.w;
            float s2 = q[8]*k2.x + q[9]*k2.y + q[10]*k2.z + q[11]*k2.w;
            const float e0 = __expf(s0), e1 = __expf(s1), e2 = __expf(s2);
            sum0 += e0; sum1 += e1; sum2 += e2;
            const float4 v0 = *(const float4*)&sV[jj][0];
            const float4 v1 = *(const float4*)&sV[jj][4];
            const float4 v2 = *(const float4*)&sV[jj][8];
            acc[0]  = fmaf(e0, v0.x, acc[0]);  acc[1]  = fmaf(e0, v0.y, acc[1]);
            acc[2]  = fmaf(e0, v0.z, acc[2]);  acc[3]  = fmaf(e0, v0.w, acc[3]);
            acc[4]  = fmaf(e1, v1.x, acc[4]);  acc[5]  = fmaf(e1, v1.y, acc[5]);
            acc[6]  = fmaf(e1, v1.z, acc[6]);  acc[7]  = fmaf(e1, v1.w, acc[7]);
            acc[8]  = fmaf(e2, v2.x, acc[8]);  acc[9]  = fmaf(e2, v2.y, acc[9]);
            acc[10] = fmaf(e2, v2.z, acc[10]); acc[11] = fmaf(e2, v2.w, acc[11]);
        }
        if (half == 1) {
            sPA[0][t] = sum0; sPA[1][t] = sum1; sPA[2][t] = sum2;
#pragma unroll
            for (int i = 0; i < HK_; i++) sPA[3 + i][t] = acc[i];
        }
        __syncthreads();
        if (half == 0) {
            sum0 += sPA[0][t]; sum1 += sPA[1][t]; sum2 += sPA[2][t];
#pragma unroll
            for (int i = 0; i < HK_; i++) acc[i] += sPA[3 + i][t];
            float s0 = q[0]*kp[0] + q[1]*kp[1] + q[2]*kp[2] + q[3]*kp[3];
            float s1 = q[4]*kp[4] + q[5]*kp[5] + q[6]*kp[6] + q[7]*kp[7];
            float s2 = q[8]*kp[8] + q[9]*kp[9] + q[10]*kp[10] + q[11]*kp[11];
            const float e0 = __expf(s0), e1 = __expf(s1), e2 = __expf(s2);
            sum0 -= e0; sum1 -= e1; sum2 -= e2;
            const float i0 = 1.f / sum0, i1 = 1.f / sum1, i2 = 1.f / sum2;
#pragma unroll
            for (int k = 0; k < K_; k++) {
                featw(OFF_F0, t, k,     fmaf(-e0, vp[k],     acc[k])     * i0 - vp[k]);
                featw(OFF_F0, t, 4 + k, fmaf(-e1, vp[4 + k], acc[4 + k]) * i1 - vp[4 + k]);
                featw(OFF_F0, t, 8 + k, fmaf(-e2, vp[8 + k], acc[8 + k]) * i2 - vp[8 + k]);
            }
#pragma unroll
            for (int c = 0; c < QD_; c++) featw(OFF_F0, t, HK_ + c, qs[c]);
        }
    }

    // ---- b1 projections (q1 persists in regs; K/V(b1) to dedicated smem) ----
    float q1[HK_];
    {
        float qs1[QD_];
        const float* st = state + (size_t)(b1 * T_ + t) * SD_;
        const float* ac = action + (size_t)(b1 * T_ + t) * AD_;
#pragma unroll
        for (int c = 0; c < SD_; c++) qs1[c] = st[c];
        qs1[SD_] = ac[0];
        qs1[SD_ + 1] = ac[1];
#pragma unroll
        for (int i = 0; i < HK_; i++) {
            float a = 0.f;
#pragma unroll
            for (int c = 0; c < QD_; c++) a = fmaf(qs1[c], Wq[i * QD_ + c], a);
            q1[i] = 0.5f * a;
        }
        if (half == 0) {
            float (*sK1)[HK_] = (float(*)[HK_])(smem + OFF_SK1);
            float (*sV1)[HK_] = (float(*)[HK_])(smem + OFF_SV1);
#pragma unroll
            for (int i = 0; i < HK_; i++) {
                float ak = 0.f, av = 0.f;
#pragma unroll
                for (int c = 0; c < K_; c++) {
                    ak = fmaf(qs1[c], Wk[i * K_ + c], ak);
                    av = fmaf(qs1[c], Wv[i * K_ + c], av);
                }
                sK1[t][i] = ak; sV1[t][i] = av;
            }
#pragma unroll
            for (int c = 0; c < QD_; c++) featw(OFF_F1, t, HK_ + c, qs1[c]);
        }
    }
    __syncthreads();

    // ---- PDL: g_W2h valid; stage panels 0,1 ----
    asm volatile("griddepcontrol.wait;" ::: "memory");
    stageB(0, 0);
    stageB(1, 1);

    // ---- warp tiling: 2(M) x 4(N), warp tile 64x64 ----
    const int mwarp = wid >> 2, nwarp = wid & 3;
    const int m0w = mwarp * 64, n0w = nwarp * 64;
    const int rsel = (ln & 7) | (((ln >> 4) & 1) << 3);
    const int cpart = (ln >> 3) & 1;
    const int swz = ln & 7;
    const uint32_t aBase = sb + OFF_A +
        (uint32_t)((m0w + (ln & 15)) * (ASTRIDE * 2) + (ln >> 4) * 16);
    const uint32_t bRow = (uint32_t)((n0w + rsel) * 128);

    // ---- W1 HMMA (single term, K=32) + h1->A; shared by both batches ----
    auto w1_to_A = [&](int offF) {
        float a1[4][8][4];
#pragma unroll
        for (int i = 0; i < 4; i++)
#pragma unroll
            for (int j = 0; j < 8; j++)
#pragma unroll
                for (int c = 0; c < 4; c++) a1[i][j][c] = 0.f;
        const int aRow = m0w + (ln & 15);
        const int aSw = (aRow >> 1) & 3;
        const int aCS = ln >> 4;
        const int bSw = (rsel >> 1) & 3;
#pragma unroll
        for (int ks = 0; ks < 2; ks++) {
            uint32_t ah[4][4], bh[4][4];
#pragma unroll
            for (int i = 0; i < 4; i++)
                ldsm4(ah[i], sb + offF + (uint32_t)((aRow + i * 16) * 64 +
                              (((ks * 2 + aCS) ^ aSw) << 4)));
#pragma unroll
            for (int j = 0; j < 4; j++)
                ldsm4(bh[j], sb + OFF_W1T + (uint32_t)((n0w + j * 16 + rsel) * 64 +
                              (((ks * 2 + cpart) ^ bSw) << 4)));
#pragma unroll
            for (int j = 0; j < 4; j++)
#pragma unroll
                for (int i = 0; i < 4; i++) {
                    mma16816(a1[i][2 * j],     ah[i], bh[j][0], bh[j][1]);
                    mma16816(a1[i][2 * j + 1], ah[i], bh[j][2], bh[j][3]);
                }
        }
#pragma unroll
        for (int i = 0; i < 4; i++) {
            const int r0 = m0w + i * 16 + (ln >> 2);
#pragma unroll
            for (int j = 0; j < 8; j++) {
                const int n = n0w + j * 8 + 2 * (ln & 3);
                const float h0 = fmaxf(a1[i][j][0] + sB1[n], 0.f);
                const float h1h = fmaxf(a1[i][j][1] + sB1[n + 1], 0.f);
                const float h2h = fmaxf(a1[i][j][2] + sB1[n], 0.f);
                const float h3 = fmaxf(a1[i][j][3] + sB1[n + 1], 0.f);
                *(uint32_t*)(smem + OFF_A + r0 * (ASTRIDE * 2) + n * 2) = packh2(h0, h1h);
                *(uint32_t*)(smem + OFF_A + (r0 + 8) * (ASTRIDE * 2) + n * 2) = packh2(h2h, h3);
            }
        }
    };

    w1_to_A(OFF_F0);
    __syncthreads();

    // ---- attention(b1) running state (interleaved into GEMM(b0)) ----
    float as0 = 0.f, as1 = 0.f, as2 = 0.f;
    float aac[HK_];
#pragma unroll
    for (int i = 0; i < HK_; i++) aac[i] = 0.f;
    const int j0b1 = half * 64;
    auto attn1_step = [&](int jj) {
        const float* kr = (const float*)(smem + OFF_SK1 + jj * 48);
        const float* vr = (const float*)(smem + OFF_SV1 + jj * 48);
        const float4 k0 = *(const float4*)(kr);
        const float4 k1 = *(const float4*)(kr + 4);
        const float4 k2 = *(const float4*)(kr + 8);
        float s0 = q1[0]*k0.x + q1[1]*k0.y + q1[2]*k0.z + q1[3]*k0.w;
        float s1 = q1[4]*k1.x + q1[5]*k1.y + q1[6]*k1.z + q1[7]*k1.w;
        float s2 = q1[8]*k2.x + q1[9]*k2.y + q1[10]*k2.z + q1[11]*k2.w;
        const float e0 = __expf(s0), e1 = __expf(s1), e2 = __expf(s2);
        as0 += e0; as1 += e1; as2 += e2;
        const float4 v0 = *(const float4*)(vr);
        const float4 v1 = *(const float4*)(vr + 4);
        const float4 v2 = *(const float4*)(vr + 8);
        aac[0]  = fmaf(e0, v0.x, aac[0]);  aac[1]  = fmaf(e0, v0.y, aac[1]);
        aac[2]  = fmaf(e0, v0.z, aac[2]);  aac[3]  = fmaf(e0, v0.w, aac[3]);
        aac[4]  = fmaf(e1, v1.x, aac[4]);  aac[5]  = fmaf(e1, v1.y, aac[5]);
        aac[6]  = fmaf(e1, v1.z, aac[6]);  aac[7]  = fmaf(e1, v1.w, aac[7]);
        aac[8]  = fmaf(e2, v2.x, aac[8]);  aac[9]  = fmaf(e2, v2.y, aac[9]);
        aac[10] = fmaf(e2, v2.z, aac[10]); aac[11] = fmaf(e2, v2.w, aac[11]);
    };

    float acc[4][8][4];
    auto epilogue = [&](float* dst) {
        float po[4][2] = {{0.f, 0.f}, {0.f, 0.f}, {0.f, 0.f}, {0.f, 0.f}};
#pragma unroll
        for (int i = 0; i < 4; i++)
#pragma unroll
            for (int j = 0; j < 8; j++) {
                const int nb = n0w + j * 8 + 2 * (ln & 3);
                const float2 bw0 = sBW[nb], bw1 = sBW[nb + 1];
                po[i][0] += fmaxf(acc[i][j][0] + bw0.x, 0.f) * bw0.y
                          + fmaxf(acc[i][j][1] + bw1.x, 0.f) * bw1.y;
                po[i][1] += fmaxf(acc[i][j][2] + bw0.x, 0.f) * bw0.y
                          + fmaxf(acc[i][j][3] + bw1.x, 0.f) * bw1.y;
            }
#pragma unroll
        for (int o = 1; o <= 2; o <<= 1)
#pragma unroll
            for (int i = 0; i < 4; i++) {
                po[i][0] += __shfl_xor_sync(0xffffffffu, po[i][0], o);
                po[i][1] += __shfl_xor_sync(0xffffffffu, po[i][1], o);
            }
        if ((ln & 3) == 0) {
            const int r = ln >> 2;
#pragma unroll
            for (int i = 0; i < 4; i++) {
                atomicAdd(&sred[m0w + i * 16 + r], po[i][0]);
                atomicAdd(&sred[m0w + i * 16 + 8 + r], po[i][1]);
            }
        }
        __syncthreads();
        if (tid < MT_) {
            dst[tid] = sred[tid] + bout[0];
            sred[tid] = 0.f;
        }
    };

    // ================= GEMM(b0) with attn(b1) interleave =================
#pragma unroll
    for (int i = 0; i < 4; i++)
#pragma unroll
        for (int j = 0; j < 8; j++)
#pragma unroll
            for (int c = 0; c < 4; c++) acc[i][j][c] = 0.f;

    for (int p = 0; p < 4; p++) {
        if (p < 3) asm volatile("cp.async.wait_group 1;" ::: "memory");
        else       asm volatile("cp.async.wait_group 0;" ::: "memory");
        __syncthreads();
        const uint32_t bBase = sb + OFF_B + (uint32_t)((p & 1) * BPANEL) + bRow;
#pragma unroll
        for (int ks = 0; ks < 4; ks++) {
            uint32_t ah[4][4], bh[4][4];
            const uint32_t ka = (uint32_t)(p * 128 + ks * 32);
#pragma unroll
            for (int i = 0; i < 4; i++)
                ldsm4(ah[i], aBase + ka + (uint32_t)(i * 16 * ASTRIDE * 2));
            const uint32_t bchunk = (uint32_t)(((ks * 2 + cpart) ^ swz) << 4);
#pragma unroll
            for (int jj = 0; jj < 4; jj++)
                ldsm4(bh[jj], bBase + bchunk + (uint32_t)(jj * 16 * 128));
#pragma unroll
            for (int jj = 0; jj < 4; jj++)
#pragma unroll
                for (int i = 0; i < 4; i++) {
                    mma16816(acc[i][2 * jj],     ah[i], bh[jj][0], bh[jj][1]);
                    mma16816(acc[i][2 * jj + 1], ah[i], bh[jj][2], bh[jj][3]);
                }
            // interleave: 4 attention(b1) iterations fill MMA dead issue slots
#pragma unroll
            for (int u = 0; u < 4; u++)
                attn1_step(j0b1 + p * 16 + ks * 4 + u);
        }
        if (p < 3) __syncthreads();
        if (p < 2) stageB(p + 2, p & 1);
    }
    __syncthreads();
    stageB(0, 0);   // restage panels for b1 under the epilogue/finalize
    stageB(1, 1);

    epilogue(out + (size_t)b0 * T_);

    // ---- finalize attention(b1) ----
    {
        float (*sPA)[MT_] = (float(*)[MT_])(smem + OFF_PA1);
        if (half == 1) {
            sPA[0][t] = as0; sPA[1][t] = as1; sPA[2][t] = as2;
#pragma unroll
            for (int i = 0; i < HK_; i++) sPA[3 + i][t] = aac[i];
        }
        __syncthreads();
        if (half == 0) {
            as0 += sPA[0][t]; as1 += sPA[1][t]; as2 += sPA[2][t];
#pragma unroll
            for (int i = 0; i < HK_; i++) aac[i] += sPA[3 + i][t];
            // recompute kp1/vp1 (cheap; keeps register peak low during GEMM)
            float qs1[QD_], kp1[HK_], vp1[HK_];
            const float* st = state + (size_t)(b1 * T_ + t) * SD_;
            const float* ac = action + (size_t)(b1 * T_ + t) * AD_;
#pragma unroll
            for (int c = 0; c < SD_; c++) qs1[c] = st[c];
            qs1[SD_] = ac[0];
            qs1[SD_ + 1] = ac[1];
#pragma unroll
            for (int i = 0; i < HK_; i++) {
                float ak = 0.f, av = 0.f;
#pragma unroll
                for (int c = 0; c < K_; c++) {
                    ak = fmaf(qs1[c], Wk[i * K_ + c], ak);
                    av = fmaf(qs1[c], Wv[i * K_ + c], av);
                }
                kp1[i] = ak; vp1[i] = av;
            }
            float s0 = q1[0]*kp1[0] + q1[1]*kp1[1] + q1[2]*kp1[2] + q1[3]*kp1[3];
            float s1 = q1[4]*kp1[4] + q1[5]*kp1[5] + q1[6]*kp1[6] + q1[7]*kp1[7];
            float s2 = q1[8]*kp1[8] + q1[9]*kp1[9] + q1[10]*kp1[10] + q1[11]*kp1[11];
            const float e0 = __expf(s0), e1 = __expf(s1), e2 = __expf(s2);
            as0 -= e0; as1 -= e1; as2 -= e2;
            const float i0 = 1.f / as0, i1 = 1.f / as1, i2 = 1.f / as2;
#pragma unroll
            for (int k = 0; k < K_; k++) {
                featw(OFF_F1, t, k,     fmaf(-e0, vp1[k],     aac[k])     * i0 - vp1[k]);
                featw(OFF_F1, t, 4 + k, fmaf(-e1, vp1[4 + k], aac[4 + k]) * i1 - vp1[4 + k]);
                featw(OFF_F1, t, 8 + k, fmaf(-e2, vp1[8 + k], aac[8 + k]) * i2 - vp1[8 + k]);
            }
        }
    }
    __syncthreads();

    // ================= batch b1: W1 + GEMM + epilogue =================
    w1_to_A(OFF_F1);
    __syncthreads();

#pragma unroll
    for (int i = 0; i < 4; i++)
#pragma unroll
        for (int j = 0; j < 8; j++)
#pragma unroll
            for (int c = 0; c < 4; c++) acc[i][j][c] = 0.f;

    for (int p = 0; p < 4; p++) {
        if (p < 3) asm volatile("cp.async.wait_group 1;" ::: "memory");
        else       asm volatile("cp.async.wait_group 0;" ::: "memory");
        __syncthreads();
        const uint32_t bBase = sb + OFF_B + (uint32_t)((p & 1) * BPANEL) + bRow;
#pragma unroll
        for (int ks = 0; ks < 4; ks++) {
            uint32_t ah[4][4], bh[4][4];
            const uint32_t ka = (uint32_t)(p * 128 + ks * 32);
#pragma unroll
            for (int i = 0; i < 4; i++)
                ldsm4(ah[i], aBase + ka + (uint32_t)(i * 16 * ASTRIDE * 2));
            const uint32_t bchunk = (uint32_t)(((ks * 2 + cpart) ^ swz) << 4);
#pragma unroll
            for (int jj = 0; jj < 4; jj++)
                ldsm4(bh[jj], bBase + bchunk + (uint32_t)(jj * 16 * 128));
#pragma unroll
            for (int jj = 0; jj < 4; jj++)
#pragma unroll
                for (int i = 0; i < 4; i++) {
                    mma16816(acc[i][2 * jj],     ah[i], bh[jj][0], bh[jj][1]);
                    mma16816(acc[i][2 * jj + 1], ah[i], bh[jj][2], bh[jj][3]);
                }
        }
        if (p < 3) __syncthreads();
        if (p < 2) stageB(p + 2, p & 1);
    }
    __syncthreads();
    epilogue(out + (size_t)b1 * T_);
}

extern "C" void kernel_launch(void* const* d_in, const int* in_sizes, int n_in,
                              void* d_out, int out_size) {
    const float* state  = (const float*)d_in[0];
    const float* action = (const float*)d_in[1];
    const float* Wk     = (const float*)d_in[2];
    const float* Wq     = (const float*)d_in[3];
    const float* Wv     = (const float*)d_in[4];
    const float* W1     = (const float*)d_in[5];
    const float* b1     = (const float*)d_in[6];
    const float* W2     = (const float*)d_in[7];
    const float* b2     = (const float*)d_in[8];
    const float* Wout   = (const float*)d_in[9];
    const float* bout   = (const float*)d_in[10];
    float* out = (float*)d_out;

    const int smem = 189440;
    cudaFuncSetAttribute(fused_kernel, cudaFuncAttributeMaxDynamicSharedMemorySize, smem);

    wsplit_kernel<<<64, 256>>>(W2);

    cudaLaunchConfig_t cfg = {};
    cfg.gridDim = dim3(B_ / 2, 1, 1);
    cfg.blockDim = dim3(256, 1, 1);
    cfg.dynamicSmemBytes = (size_t)smem;
    cfg.stream = 0;
    cudaLaunchAttribute attrs[1];
    attrs[0].id = cudaLaunchAttributeProgrammaticStreamSerialization;
    attrs[0].val.programmaticStreamSerializationAllowed = 1;
    cfg.attrs = attrs;
    cfg.numAttrs = 1;
    cudaLaunchKernelEx(&cfg, fused_kernel, state, action, Wk, Wq, Wv,
                       W1, b1, b2, Wout, bout, out);
}